// round 4
// baseline (speedup 1.0000x reference)
#include <cuda_runtime.h>
#include <cuda_bf16.h>

// CPDecoding: out[n] = sum_c prod_d lerp(line_coef[d][c], pos_d(n))
// coords stacked (z,y,x): table dim d uses input column (2-d).
//
// R4: split the coefficient table across the two idle-vs-busy memory ports.
//  - comps 0..15: SMEM diff-table, 8 float4 per row (128-B stride -> every
//    row phase-aligned; 8 lanes read 8 consecutive float4 of one row = one
//    conflict-free 128-B phase per point-dim; was 2 phases).
//  - comps 16..23: __device__ global diff-table (48 KB, L2-resident), read
//    with __ldcg (L2-only, bypasses the saturated l1tex data path) on lanes
//    0-3; 64-B aligned rows -> 2 sectors. 6 LDGs issued up-front (MLP=6).
// Lanes 4-7 get G=0 -> their global products vanish; no mask needed.

#define NCOMP  24
#define RES    256
#define SROWF4 8      // smem float4 per row (comps 0..15), 128-B stride
#define GROWF4 4      // gmem float4 per row (comps 16..23), 64-B stride
#define STAB_F4 (3 * RES * SROWF4)    // 6144 float4 = 98304 B

__device__ float4 g_tab[3 * RES * GROWF4];   // 49152 B, L2-resident

__global__ void build_gtab_kernel(const float* __restrict__ coef)
{
    int e = blockIdx.x * blockDim.x + threadIdx.x;
    if (e >= 3 * RES * GROWF4) return;
    int d   = e / (RES * GROWF4);
    int rem = e - d * (RES * GROWF4);
    int i   = rem / GROWF4;
    int j   = rem - i * GROWF4;
    int c0  = 16 + 2 * j;
    const float* ca = coef + (d * NCOMP + c0) * RES;
    const float* cb = ca + RES;
    float a0 = __ldg(ca + i);
    float a1 = (i < RES - 1) ? __ldg(ca + i + 1) : a0;
    float b0 = __ldg(cb + i);
    float b1 = (i < RES - 1) ? __ldg(cb + i + 1) : b0;
    g_tab[e] = make_float4(a0, a1 - a0, b0, b1 - b0);
}

__global__ __launch_bounds__(1024, 1)
void cp_decode_kernel(const float* __restrict__ pts,
                      const float* __restrict__ coef,
                      float* __restrict__ out,
                      int npts)
{
    extern __shared__ float4 tab[];

    // ---- Build SMEM diff table (comps 0..15): tab[(d*256+i)*8+j] ----
    const int tid = threadIdx.x;
    for (int e = tid; e < STAB_F4; e += blockDim.x) {
        int d   = e / (RES * SROWF4);
        int rem = e - d * (RES * SROWF4);
        int i   = rem / SROWF4;
        int j   = rem - i * SROWF4;
        const float* ca = coef + (d * NCOMP + 2 * j) * RES;
        const float* cb = ca + RES;
        float a0 = __ldg(ca + i);
        float a1 = (i < RES - 1) ? __ldg(ca + i + 1) : a0;
        float b0 = __ldg(cb + i);
        float b1 = (i < RES - 1) ? __ldg(cb + i + 1) : b0;
        tab[e] = make_float4(a0, a1 - a0, b0, b1 - b0);
    }
    __syncthreads();

    const int lane   = tid & 31;
    const int gwarp  = (blockIdx.x * blockDim.x + tid) >> 5;
    const int nwarps = (gridDim.x * blockDim.x) >> 5;

    const int p    = lane >> 3;      // point slot in group of 4
    const int sub  = lane & 7;       // lane within point
    const bool gld = (sub < 4);      // lanes doing the global half

    const int niters = (npts + 7) >> 3;    // 8 points per iter

    // Prologue: stage coords for first iteration (lanes 0..23).
    int iter = gwarp;
    float v = 0.0f;
    if (iter < niters) {
        int fl = iter * 24 + lane;
        if (lane < 24 && fl < npts * 3) v = __ldg(pts + fl);
    }

    for (; iter < niters; iter += nwarps) {
        const int base = iter << 3;

        // Per-dim sample positions for both groups.
        int   iA[3], iB[3];
        float wA[3], wB[3];
        #pragma unroll
        for (int d = 0; d < 3; d++) {
            float xA = __shfl_sync(0xffffffffu, v, p * 3 + (2 - d));
            float xB = __shfl_sync(0xffffffffu, v, 12 + p * 3 + (2 - d));
            float posA = fmaf(xA, 127.5f, 127.5f);
            float posB = fmaf(xB, 127.5f, 127.5f);
            float fA = floorf(posA), fB = floorf(posB);
            wA[d] = posA - fA;        wB[d] = posB - fB;
            iA[d] = min(max((int)fA, 0), RES - 1);
            iB[d] = min(max((int)fB, 0), RES - 1);
        }

        // Issue all 6 global loads early (MLP=6, L2-only path).
        float4 GA[3], GB[3];
        #pragma unroll
        for (int d = 0; d < 3; d++) {
            GA[d] = gld ? __ldcg(&g_tab[(d * RES + iA[d]) * GROWF4 + sub])
                        : make_float4(0.f, 0.f, 0.f, 0.f);
            GB[d] = gld ? __ldcg(&g_tab[(d * RES + iB[d]) * GROWF4 + sub])
                        : make_float4(0.f, 0.f, 0.f, 0.f);
        }

        // Prefetch next iteration's coords.
        float vn = 0.0f;
        {
            int itn = iter + nwarps;
            int fl = itn * 24 + lane;
            if (itn < niters && lane < 24 && fl < npts * 3)
                vn = __ldg(pts + fl);
        }

        // SMEM halves (comps 2sub, 2sub+1 -> 16 comps over 8 lanes).
        float accA, accB;
        {
            float L0[3], L1[3];
            #pragma unroll
            for (int d = 0; d < 3; d++) {
                float4 Aq = tab[(d * RES + iA[d]) * SROWF4 + sub];
                L0[d] = fmaf(wA[d], Aq.y, Aq.x);
                L1[d] = fmaf(wA[d], Aq.w, Aq.z);
            }
            accA = fmaf(L1[0] * L1[1], L1[2], L0[0] * L0[1] * L0[2]);
        }
        {
            float L0[3], L1[3];
            #pragma unroll
            for (int d = 0; d < 3; d++) {
                float4 Aq = tab[(d * RES + iB[d]) * SROWF4 + sub];
                L0[d] = fmaf(wB[d], Aq.y, Aq.x);
                L1[d] = fmaf(wB[d], Aq.w, Aq.z);
            }
            accB = fmaf(L1[0] * L1[1], L1[2], L0[0] * L0[1] * L0[2]);
        }

        // Global halves (comps 16+2sub, 17+2sub on lanes 0-3; zeros else).
        {
            float M0[3], M1[3];
            #pragma unroll
            for (int d = 0; d < 3; d++) {
                M0[d] = fmaf(wA[d], GA[d].y, GA[d].x);
                M1[d] = fmaf(wA[d], GA[d].w, GA[d].z);
            }
            accA = fmaf(M0[0] * M0[1], M0[2], accA);
            accA = fmaf(M1[0] * M1[1], M1[2], accA);
        }
        {
            float M0[3], M1[3];
            #pragma unroll
            for (int d = 0; d < 3; d++) {
                M0[d] = fmaf(wB[d], GB[d].y, GB[d].x);
                M1[d] = fmaf(wB[d], GB[d].w, GB[d].z);
            }
            accB = fmaf(M0[0] * M0[1], M0[2], accB);
            accB = fmaf(M1[0] * M1[1], M1[2], accB);
        }

        // Two independent 8-lane reductions, interleaved.
        #pragma unroll
        for (int s = 4; s; s >>= 1) {
            accA += __shfl_xor_sync(0xffffffffu, accA, s);
            accB += __shfl_xor_sync(0xffffffffu, accB, s);
        }

        if (sub == 0) {
            int pA = base + p;
            int pB = base + 4 + p;
            if (pA < npts) out[pA] = accA;
            if (pB < npts) out[pB] = accB;
        }

        v = vn;
    }
}

extern "C" void kernel_launch(void* const* d_in, const int* in_sizes, int n_in,
                              void* d_out, int out_size)
{
    const float* pts  = (const float*)d_in[0];   // [N,3] float32
    const float* coef = (const float*)d_in[1];   // [3,24,256] float32
    float* out = (float*)d_out;

    const int npts = in_sizes[0] / 3;
    const size_t smem = STAB_F4 * sizeof(float4); // 98304 B

    cudaFuncSetAttribute(cp_decode_kernel,
                         cudaFuncAttributeMaxDynamicSharedMemorySize,
                         (int)smem);

    build_gtab_kernel<<<3, 1024>>>(coef);
    cp_decode_kernel<<<148, 1024, smem>>>(pts, coef, out, npts);
}

// round 5
// speedup vs baseline: 1.4969x; 1.4969x over previous
#include <cuda_runtime.h>
#include <cuda_fp16.h>

// CPDecoding: out[n] = sum_c prod_d lerp(line_coef[d][c], pos_d(n))
// coords stacked (z,y,x): table dim d uses input column (2-d).
//
// R5: fp16 diff table so one whole 24-component row fits in a single 128-B
// shared line -> ONE LDS.128 wavefront per point-dim (R3 needed two: l1tex
// wavefronts = distinct 128B lines touched per instruction, one per point,
// independent of useful bytes -- so the only win is fewer instructions).
// Row layout (128 B, aligned): 12x uint2 {half2(f0_c,f0_c+1), half2(d_c,d_c+1)}
// + 32 B zero pad. Lane sub (0..7) reads uint4 = comps 4sub..4sub+3; lanes
// 6,7 read the zero pad -> contribute exactly 0, no masking needed.
// Lerp in HFMA2, widen to fp32 for products + reduction (no half accumulate).
// 8 points/warp-iter (2 groups), pipelined coord loads. Single kernel (R4's
// second kernel cost ~11us of graph overhead).

#define NCOMP 24
#define RES   256
#define ROWU2 16                        // uint2 slots per row (12 data + 4 pad)
#define TAB_U2 (3 * RES * ROWU2)        // 12288 uint2 = 98304 B

__global__ __launch_bounds__(1024, 1)
void cp_decode_kernel(const float* __restrict__ pts,
                      const float* __restrict__ coef,
                      float* __restrict__ out,
                      int npts)
{
    extern __shared__ uint2 tabu2[];

    // ---- Build fp16 diff table ----
    const int tid = threadIdx.x;
    for (int e = tid; e < TAB_U2; e += blockDim.x) {
        int d   = e / (RES * ROWU2);
        int rem = e - d * (RES * ROWU2);
        int i   = rem / ROWU2;
        int j   = rem - i * ROWU2;
        uint2 val = make_uint2(0u, 0u);
        if (j < 12) {
            const float* ca = coef + (d * NCOMP + 2 * j) * RES;
            const float* cb = ca + RES;
            float a0 = __ldg(ca + i);
            float a1 = (i < RES - 1) ? __ldg(ca + i + 1) : a0;
            float b0 = __ldg(cb + i);
            float b1 = (i < RES - 1) ? __ldg(cb + i + 1) : b0;
            __half2 f0 = __floats2half2_rn(a0, b0);
            __half2 df = __floats2half2_rn(a1 - a0, b1 - b0);
            val.x = *reinterpret_cast<unsigned*>(&f0);
            val.y = *reinterpret_cast<unsigned*>(&df);
        }
        tabu2[e] = val;
    }
    __syncthreads();

    const uint4* __restrict__ tab4 = reinterpret_cast<const uint4*>(tabu2);

    const int lane   = tid & 31;
    const int gwarp  = (blockIdx.x * blockDim.x + tid) >> 5;
    const int nwarps = (gridDim.x * blockDim.x) >> 5;

    const int p   = lane >> 3;       // point slot in group of 4
    const int sub = lane & 7;        // lane within point (comps 4sub..4sub+3)

    const int niters = (npts + 7) >> 3;    // 8 points per iter

    // Prologue: stage first iteration's 24 coords on lanes 0..23.
    int iter = gwarp;
    float v = 0.0f;
    if (iter < niters) {
        int fl = iter * 24 + lane;
        if (lane < 24 && fl < npts * 3) v = __ldg(pts + fl);
    }

    for (; iter < niters; iter += nwarps) {
        const int base = iter << 3;

        // Per-dim sample index + weight for both groups.
        int   iA[3], iB[3];
        float wAf[3], wBf[3];
        #pragma unroll
        for (int d = 0; d < 3; d++) {
            float xA = __shfl_sync(0xffffffffu, v, p * 3 + (2 - d));
            float xB = __shfl_sync(0xffffffffu, v, 12 + p * 3 + (2 - d));
            float posA = fmaf(xA, 127.5f, 127.5f);
            float posB = fmaf(xB, 127.5f, 127.5f);
            float fA = floorf(posA), fB = floorf(posB);
            wAf[d] = posA - fA;       wBf[d] = posB - fB;
            iA[d] = min(max((int)fA, 0), RES - 1);
            iB[d] = min(max((int)fB, 0), RES - 1);
        }

        // Prefetch next iteration's coords.
        float vn = 0.0f;
        {
            int itn = iter + nwarps;
            int fl = itn * 24 + lane;
            if (itn < niters && lane < 24 && fl < npts * 3)
                vn = __ldg(pts + fl);
        }

        // ---- group A ----
        float2 a0_, a1_, a2_, b0_, b1_, b2_;
        {
            float2 LA[3], LB[3];
            #pragma unroll
            for (int d = 0; d < 3; d++) {
                uint4 q = tab4[(d * RES + iA[d]) * 8 + sub];
                __half2 w2  = __float2half2_rn(wAf[d]);
                __half2 f0a = *reinterpret_cast<__half2*>(&q.x);
                __half2 dfa = *reinterpret_cast<__half2*>(&q.y);
                __half2 f0b = *reinterpret_cast<__half2*>(&q.z);
                __half2 dfb = *reinterpret_cast<__half2*>(&q.w);
                LA[d] = __half22float2(__hfma2(w2, dfa, f0a));
                LB[d] = __half22float2(__hfma2(w2, dfb, f0b));
            }
            a0_ = LA[0]; a1_ = LA[1]; a2_ = LA[2];
            b0_ = LB[0]; b1_ = LB[1]; b2_ = LB[2];
        }
        float accA;
        {
            float t0 = (a0_.x * a1_.x) * a2_.x;
            float t1 = fmaf(a0_.y * a1_.y, a2_.y, t0);
            float t2 = fmaf(b0_.x * b1_.x, b2_.x, t1);
            accA     = fmaf(b0_.y * b1_.y, b2_.y, t2);
        }

        // ---- group B ----
        {
            float2 LA[3], LB[3];
            #pragma unroll
            for (int d = 0; d < 3; d++) {
                uint4 q = tab4[(d * RES + iB[d]) * 8 + sub];
                __half2 w2  = __float2half2_rn(wBf[d]);
                __half2 f0a = *reinterpret_cast<__half2*>(&q.x);
                __half2 dfa = *reinterpret_cast<__half2*>(&q.y);
                __half2 f0b = *reinterpret_cast<__half2*>(&q.z);
                __half2 dfb = *reinterpret_cast<__half2*>(&q.w);
                LA[d] = __half22float2(__hfma2(w2, dfa, f0a));
                LB[d] = __half22float2(__hfma2(w2, dfb, f0b));
            }
            a0_ = LA[0]; a1_ = LA[1]; a2_ = LA[2];
            b0_ = LB[0]; b1_ = LB[1]; b2_ = LB[2];
        }
        float accB;
        {
            float t0 = (a0_.x * a1_.x) * a2_.x;
            float t1 = fmaf(a0_.y * a1_.y, a2_.y, t0);
            float t2 = fmaf(b0_.x * b1_.x, b2_.x, t1);
            accB     = fmaf(b0_.y * b1_.y, b2_.y, t2);
        }

        // Two independent 8-lane reductions, interleaved.
        #pragma unroll
        for (int s = 4; s; s >>= 1) {
            accA += __shfl_xor_sync(0xffffffffu, accA, s);
            accB += __shfl_xor_sync(0xffffffffu, accB, s);
        }

        if (sub == 0) {
            int pA = base + p;
            int pB = base + 4 + p;
            if (pA < npts) out[pA] = accA;
            if (pB < npts) out[pB] = accB;
        }

        v = vn;
    }
}

extern "C" void kernel_launch(void* const* d_in, const int* in_sizes, int n_in,
                              void* d_out, int out_size)
{
    const float* pts  = (const float*)d_in[0];   // [N,3] float32
    const float* coef = (const float*)d_in[1];   // [3,24,256] float32
    float* out = (float*)d_out;

    const int npts = in_sizes[0] / 3;
    const size_t smem = TAB_U2 * sizeof(uint2);  // 98304 B

    cudaFuncSetAttribute(cp_decode_kernel,
                         cudaFuncAttributeMaxDynamicSharedMemorySize,
                         (int)smem);

    cp_decode_kernel<<<148, 1024, smem>>>(pts, coef, out, npts);
}